// round 17
// baseline (speedup 1.0000x reference)
#include <cuda_runtime.h>
#include <cuda_fp16.h>
#include <math.h>

#define NN  50000
#define NE  800000
#define H   96
#define IND 256

// Scratch (__device__ globals per allocation rules)
// g_qh row m (192 halves): entry j (uint2): .x = q half2 (cols 2j,2j+1),
//                                           .y = hd half2 (cols 2j,2j+1)
__device__ float  g_h [(size_t)NN * H];       // h fp32 (GEMM input for p/q)
__device__ __half g_qh[(size_t)NN * 2 * H];
__device__ __half g_p [(size_t)NN * H];       // (h@Wgd^T + b_gate)/sqrt(192)
__device__ float  g_y [(size_t)NN * 2];       // logits accumulator

__device__ __forceinline__ float tanh_fast(float x) {
    float r;
    asm("tanh.approx.f32 %0, %1;" : "=f"(r) : "f"(x));
    return r;
}

// ---------------------------------------------------------------------------
// h-GEMM: h -> g_h (fp32), hd = h*d -> g_qh interleaved (fp16).
// Also zeroes g_y in its prologue. BM=64, BN=96, BK=16, 256 threads.
// ---------------------------------------------------------------------------
__global__ void __launch_bounds__(256, 5)
gemm_h(const float* __restrict__ A,      // x [NN, 256]
       const float* __restrict__ W,      // W_in [96, 256]
       const float* __restrict__ bias,   // b_in [96]
       const float* __restrict__ dvec,   // d [NN]
       float*  __restrict__ Ch,
       __half* __restrict__ qh_out,
       float*  __restrict__ yacc)
{
    __shared__ __align__(16) float As[16][68];
    __shared__ __align__(16) float Bs[16][96];

    const int tid = threadIdx.x;
    const int tx  = tid & 31;
    const int ty  = tid >> 5;
    const int m0  = blockIdx.x * 64;

    // zero y accumulator (covers NN*2 = 100000 floats with 391 blocks)
    if (blockIdx.x < 391) {
        int base = blockIdx.x * 256 + tid;
        if (base < NN * 2) yacc[base] = 0.f;
    }

    float acc[8][3];
#pragma unroll
    for (int i = 0; i < 8; ++i)
#pragma unroll
        for (int j = 0; j < 3; ++j) acc[i][j] = 0.f;

    for (int k0 = 0; k0 < IND; k0 += 16) {
        {
            int row  = tid >> 2;
            int kseg = (tid & 3) << 2;
            float4 v = make_float4(0.f, 0.f, 0.f, 0.f);
            int gm = m0 + row;
            if (gm < NN)
                v = *(const float4*)(A + (size_t)gm * IND + k0 + kseg);
            As[kseg + 0][row] = v.x;
            As[kseg + 1][row] = v.y;
            As[kseg + 2][row] = v.z;
            As[kseg + 3][row] = v.w;
        }
        for (int i = tid; i < 96 * 16; i += 256) {
            int n = i >> 4, k = i & 15;
            Bs[k][n] = W[(size_t)n * IND + k0 + k];
        }
        __syncthreads();

#pragma unroll
        for (int k = 0; k < 16; ++k) {
            float b0 = Bs[k][tx], b1 = Bs[k][tx + 32], b2 = Bs[k][tx + 64];
            float4 a0 = *(const float4*)&As[k][ty * 8];
            float4 a1 = *(const float4*)&As[k][ty * 8 + 4];
            acc[0][0] += a0.x * b0; acc[0][1] += a0.x * b1; acc[0][2] += a0.x * b2;
            acc[1][0] += a0.y * b0; acc[1][1] += a0.y * b1; acc[1][2] += a0.y * b2;
            acc[2][0] += a0.z * b0; acc[2][1] += a0.z * b1; acc[2][2] += a0.z * b2;
            acc[3][0] += a0.w * b0; acc[3][1] += a0.w * b1; acc[3][2] += a0.w * b2;
            acc[4][0] += a1.x * b0; acc[4][1] += a1.x * b1; acc[4][2] += a1.x * b2;
            acc[5][0] += a1.y * b0; acc[5][1] += a1.y * b1; acc[5][2] += a1.y * b2;
            acc[6][0] += a1.z * b0; acc[6][1] += a1.z * b1; acc[6][2] += a1.z * b2;
            acc[7][0] += a1.w * b0; acc[7][1] += a1.w * b1; acc[7][2] += a1.w * b2;
        }
        __syncthreads();
    }

    const float bb0 = bias[tx], bb1 = bias[tx + 32], bb2 = bias[tx + 64];
    // hd position for column c: (c>>1)*4 + 2 + (c&1)
    const int ho0 = ((tx      ) >> 1) * 4 + 2 + (tx & 1);
    const int ho1 = ((tx + 32 ) >> 1) * 4 + 2 + (tx & 1);
    const int ho2 = ((tx + 64 ) >> 1) * 4 + 2 + (tx & 1);

#pragma unroll
    for (int i = 0; i < 8; ++i) {
        int m = m0 + ty * 8 + i;
        if (m < NN) {
            float dn = __ldg(dvec + m);
            float h0 = acc[i][0] + bb0;
            float h1 = acc[i][1] + bb1;
            float h2 = acc[i][2] + bb2;
            float* hr = Ch + (size_t)m * H;
            hr[tx] = h0;  hr[tx + 32] = h1;  hr[tx + 64] = h2;
            __half* qr = qh_out + (size_t)m * (2 * H);
            qr[ho0] = __float2half(h0 * dn);
            qr[ho1] = __float2half(h1 * dn);
            qr[ho2] = __float2half(h2 * dn);
        }
    }
}

// ---------------------------------------------------------------------------
// 96-col GEMM over h: C = (h@Wg_half^T + bias)*ic, fp16 out.
// mode 0: plain rows -> p_out ; mode 1: interleaved q positions -> qh_out.
// ---------------------------------------------------------------------------
__global__ void __launch_bounds__(256, 5)
gemm96pq(const float* __restrict__ A,     // g_h [NN, 96]
         const float* __restrict__ W,     // W_gate [96, 192]
         const float* __restrict__ bias,  // b_gate or null
         __half* __restrict__ C,
         int koff, int mode, float scale)
{
    __shared__ __align__(16) float As[16][68];
    __shared__ __align__(16) float Bs[16][96];

    const int tid = threadIdx.x;
    const int tx  = tid & 31;
    const int ty  = tid >> 5;
    const int m0  = blockIdx.x * 64;

    float acc[8][3];
#pragma unroll
    for (int i = 0; i < 8; ++i)
#pragma unroll
        for (int j = 0; j < 3; ++j) acc[i][j] = 0.f;

    for (int k0 = 0; k0 < H; k0 += 16) {
        {
            int row  = tid >> 2;
            int kseg = (tid & 3) << 2;
            float4 v = make_float4(0.f, 0.f, 0.f, 0.f);
            int gm = m0 + row;
            if (gm < NN)
                v = *(const float4*)(A + (size_t)gm * H + k0 + kseg);
            As[kseg + 0][row] = v.x;
            As[kseg + 1][row] = v.y;
            As[kseg + 2][row] = v.z;
            As[kseg + 3][row] = v.w;
        }
        for (int i = tid; i < 96 * 16; i += 256) {
            int n = i >> 4, k = i & 15;
            Bs[k][n] = W[(size_t)n * (2 * H) + koff + k0 + k];
        }
        __syncthreads();

#pragma unroll
        for (int k = 0; k < 16; ++k) {
            float b0 = Bs[k][tx], b1 = Bs[k][tx + 32], b2 = Bs[k][tx + 64];
            float4 a0 = *(const float4*)&As[k][ty * 8];
            float4 a1 = *(const float4*)&As[k][ty * 8 + 4];
            acc[0][0] += a0.x * b0; acc[0][1] += a0.x * b1; acc[0][2] += a0.x * b2;
            acc[1][0] += a0.y * b0; acc[1][1] += a0.y * b1; acc[1][2] += a0.y * b2;
            acc[2][0] += a0.z * b0; acc[2][1] += a0.z * b1; acc[2][2] += a0.z * b2;
            acc[3][0] += a0.w * b0; acc[3][1] += a0.w * b1; acc[3][2] += a0.w * b2;
            acc[4][0] += a1.x * b0; acc[4][1] += a1.x * b1; acc[4][2] += a1.x * b2;
            acc[5][0] += a1.y * b0; acc[5][1] += a1.y * b1; acc[5][2] += a1.y * b2;
            acc[6][0] += a1.z * b0; acc[6][1] += a1.z * b1; acc[6][2] += a1.z * b2;
            acc[7][0] += a1.w * b0; acc[7][1] += a1.w * b1; acc[7][2] += a1.w * b2;
        }
        __syncthreads();
    }

    float bb0 = bias ? bias[tx]      : 0.f;
    float bb1 = bias ? bias[tx + 32] : 0.f;
    float bb2 = bias ? bias[tx + 64] : 0.f;

    if (mode == 0) {
#pragma unroll
        for (int i = 0; i < 8; ++i) {
            int m = m0 + ty * 8 + i;
            if (m < NN) {
                __half* cr = C + (size_t)m * H;
                cr[tx]      = __float2half((acc[i][0] + bb0) * scale);
                cr[tx + 32] = __float2half((acc[i][1] + bb1) * scale);
                cr[tx + 64] = __float2half((acc[i][2] + bb2) * scale);
            }
        }
    } else {
        // q position for column c: (c>>1)*4 + (c&1)
        const int qo0 = ((tx      ) >> 1) * 4 + (tx & 1);
        const int qo1 = ((tx + 32 ) >> 1) * 4 + (tx & 1);
        const int qo2 = ((tx + 64 ) >> 1) * 4 + (tx & 1);
#pragma unroll
        for (int i = 0; i < 8; ++i) {
            int m = m0 + ty * 8 + i;
            if (m < NN) {
                __half* qr = C + (size_t)m * (2 * H);
                qr[qo0] = __float2half((acc[i][0] + bb0) * scale);
                qr[qo1] = __float2half((acc[i][1] + bb1) * scale);
                qr[qo2] = __float2half((acc[i][2] + bb2) * scale);
            }
        }
    }
}

// ---------------------------------------------------------------------------
// Edge kernel: each warp owns 4 edges; 2 gathers per edge (p uint2 + qh uint4).
// ---------------------------------------------------------------------------
__global__ void __launch_bounds__(256)
edge_kernel(const int* __restrict__ src,
            const int* __restrict__ dst,
            const float* __restrict__ Wc,
            float* __restrict__ a_out,
            float* __restrict__ y)
{
    __shared__ __align__(16) float4 sW[48];   // Wc[2,96] as 48 float4
    const int tid = threadIdx.x;
    if (tid < 48) sW[tid] = ((const float4*)Wc)[tid];
    __syncthreads();

    const int warp = blockIdx.x * 8 + (tid >> 5);
    const int lane = tid & 31;
    const int e0   = warp * 4;                 // grid covers NE exactly

    const int4 sv = __ldg((const int4*)src + warp);
    const int4 tv = __ldg((const int4*)dst + warp);
    const int si[4] = {sv.x, sv.y, sv.z, sv.w};
    const int ti[4] = {tv.x, tv.y, tv.z, tv.w};

    float r0[4] = {0.f, 0.f, 0.f, 0.f};
    float r1[4] = {0.f, 0.f, 0.f, 0.f};

    if (lane < 24) {
        uint2 pr[4];
        uint4 qh[4];
#pragma unroll
        for (int i = 0; i < 4; ++i) {
            pr[i] = __ldg((const uint2*)(g_p  + (size_t)ti[i] * H) + lane);
            qh[i] = __ldg((const uint4*)(g_qh + (size_t)si[i] * (2 * H)) + lane);
        }

        const float4 w0 = sW[lane];
        const float4 w1 = sW[24 + lane];

#pragma unroll
        for (int i = 0; i < 4; ++i) {
            const float2 p0 = __half22float2(*(const __half2*)&pr[i].x);
            const float2 p1 = __half22float2(*(const __half2*)&pr[i].y);
            const float2 q0 = __half22float2(*(const __half2*)&qh[i].x);
            const float2 h0 = __half22float2(*(const __half2*)&qh[i].y);
            const float2 q1 = __half22float2(*(const __half2*)&qh[i].z);
            const float2 h1 = __half22float2(*(const __half2*)&qh[i].w);

            float4 av;
            av.x = tanh_fast(p0.x + q0.x);
            av.y = tanh_fast(p0.y + q0.y);
            av.z = tanh_fast(p1.x + q1.x);
            av.w = tanh_fast(p1.y + q1.y);

            __stcs(((float4*)a_out) + (size_t)(e0 + i) * 24 + lane, av);

            const float4 mv = make_float4(av.x * h0.x, av.y * h0.y,
                                          av.z * h1.x, av.w * h1.y);
            r0[i] = mv.x * w0.x + mv.y * w0.y + mv.z * w0.z + mv.w * w0.w;
            r1[i] = mv.x * w1.x + mv.y * w1.y + mv.z * w1.z + mv.w * w1.w;
        }
    }

#pragma unroll
    for (int o = 16; o; o >>= 1) {
#pragma unroll
        for (int i = 0; i < 4; ++i) {
            r0[i] += __shfl_xor_sync(0xffffffffu, r0[i], o);
            r1[i] += __shfl_xor_sync(0xffffffffu, r1[i], o);
        }
    }

    if (lane < 4) {
        float v0, v1;
        switch (lane) {
            case 0: v0 = r0[0]; v1 = r1[0]; break;
            case 1: v0 = r0[1]; v1 = r1[1]; break;
            case 2: v0 = r0[2]; v1 = r1[2]; break;
            default: v0 = r0[3]; v1 = r1[3]; break;
        }
        float* yp = y + (size_t)ti[lane] * 2;
        asm volatile("red.global.add.v2.f32 [%0], {%1, %2};"
                     :: "l"(yp), "f"(v0), "f"(v1) : "memory");
    }
}

// ---------------------------------------------------------------------------
__global__ void clf_kernel(const float* __restrict__ y,
                           const float* __restrict__ dvec,
                           const float* __restrict__ bc,
                           float* __restrict__ out)
{
    int n = blockIdx.x * blockDim.x + threadIdx.x;
    if (n >= NN) return;
    float dn = dvec[n];
    float2 yv = *(const float2*)(y + 2 * n);
    float y0 = dn * yv.x + bc[0];
    float y1 = dn * yv.y + bc[1];
    float m  = fmaxf(y0, y1);
    float lse = m + logf(expf(y0 - m) + expf(y1 - m));
    *(float2*)(out + 2 * n) = make_float2(y0 - lse, y1 - lse);
}

// ---------------------------------------------------------------------------
extern "C" void kernel_launch(void* const* d_in, const int* in_sizes, int n_in,
                              void* d_out, int out_size)
{
    const float* x      = (const float*)d_in[0];
    const float* d      = (const float*)d_in[1];
    const int*   src    = (const int*)  d_in[2];
    const int*   dst    = (const int*)  d_in[3];
    const float* W_in   = (const float*)d_in[4];
    const float* b_in   = (const float*)d_in[5];
    const float* W_gate = (const float*)d_in[6];
    const float* b_gate = (const float*)d_in[7];
    const float* W_clf  = (const float*)d_in[8];
    const float* b_clf  = (const float*)d_in[9];
    float* out = (float*)d_out;

    float  *hp, *yp;
    __half *qhp, *pp;
    cudaGetSymbolAddress((void**)&hp,  g_h);
    cudaGetSymbolAddress((void**)&qhp, g_qh);
    cudaGetSymbolAddress((void**)&pp,  g_p);
    cudaGetSymbolAddress((void**)&yp,  g_y);

    const float ic = 0.07216878364870322f;   // 1/sqrt(192)

    // h -> g_h fp32, hd -> g_qh fp16 (also zeroes g_y)
    gemm_h<<<(NN + 63) / 64, 256>>>(x, W_in, b_in, d, hp, qhp, yp);
    // p'' = (h@Wgd^T + b_gate)*ic -> g_p
    gemm96pq<<<(NN + 63) / 64, 256>>>(hp, W_gate, b_gate, pp,  0, 0, ic);
    // q'' = (h@Wgs^T)*ic -> g_qh (interleaved)
    gemm96pq<<<(NN + 63) / 64, 256>>>(hp, W_gate, nullptr, qhp, H, 1, ic);

    // edges: a (tuple order: z first, then a) + logits scatter
    edge_kernel<<<NE / 32, 256>>>(src, dst, W_clf, out + 2 * NN, yp);

    clf_kernel<<<(NN + 255) / 256, 256>>>(yp, d, b_clf, out);
}